// round 1
// baseline (speedup 1.0000x reference)
#include <cuda_runtime.h>
#include <cstdint>

// ---------------------------------------------------------------------------
// GATv2 collapsed:
//   out[e] = leaky_relu( P[src[e]] + Q[dst[e]] ) . w2 + b2
// where   P = node_feat @ (W_node @ W_a1[:128])   + b_node @ W_a1[:128]
//         Q = node_feat @ (W_node @ W_a1[128:])   + b_node @ W_a1[128:] + b_a1
// (layer loop is idempotent; edge-hidden path is dead code)
// ---------------------------------------------------------------------------

#define CH 128
#define MAX_NODES 10240
#define MAX_K 128

// scratch (no allocations allowed -> device globals)
__device__ float g_PQ[MAX_NODES * 2 * CH];   // per node: [P(128) | Q(128)]
__device__ float g_Wc[MAX_K * 2 * CH];       // combined weight [K, 256]
__device__ float g_bc[2 * CH];               // combined bias   [256]

// ---------------------------------------------------------------------------
// Kernel 1: build combined weights  Wc[K,256], bc[256]   (tiny: ~8 MFLOP)
// block j (0..255) computes column j; half 0 = P-col, half 1 = Q-col
// ---------------------------------------------------------------------------
__global__ void build_wc_kernel(const float* __restrict__ W_node,   // [K,128]
                                const float* __restrict__ b_node,   // [128]
                                const float* __restrict__ W_a1,     // [256,128]
                                const float* __restrict__ b_a1,     // [128]
                                int K) {
    int j    = blockIdx.x;       // 0..255
    int half = j >> 7;
    int c    = j & (CH - 1);
    __shared__ float col[CH];
    int t = threadIdx.x;         // 0..127
    col[t] = W_a1[(half * CH + t) * CH + c];
    __syncthreads();

    if (t < K) {
        const float* wrow = W_node + t * CH;
        float s = 0.f;
#pragma unroll 8
        for (int k = 0; k < CH; k++) s += wrow[k] * col[k];
        g_Wc[t * (2 * CH) + j] = s;
    }
    if (t == 0) {
        float s = 0.f;
        for (int k = 0; k < CH; k++) s += b_node[k] * col[k];
        if (half) s += b_a1[c];
        g_bc[j] = s;
    }
}

// ---------------------------------------------------------------------------
// Kernel 2: SGEMM  g_PQ[M,256] = node_feat[M,K] @ g_Wc[K,256] + g_bc
// 128x128 tile, BK=8, 8x8 per thread, 256 threads
// ---------------------------------------------------------------------------
__global__ __launch_bounds__(256) void sgemm_bias_kernel(
    const float* __restrict__ A, int M, int K) {
    const int N = 2 * CH;
    __shared__ float As[8][128];
    __shared__ float Bs[8][128];

    int brow = blockIdx.x * 128;
    int bcol = blockIdx.y * 128;
    int tid  = threadIdx.x;
    int tr   = (tid >> 4) * 8;       // 0..120
    int tc   = (tid & 15) * 8;       // 0..120

    float acc[8][8] = {};

    int aRow = tid >> 1;             // 0..127
    int aK   = (tid & 1) * 4;        // 0 or 4
    int bK   = tid >> 5;             // 0..7
    int bN   = (tid & 31) * 4;       // 0..124

    for (int k0 = 0; k0 < K; k0 += 8) {
        int m = brow + aRow;
#pragma unroll
        for (int i = 0; i < 4; i++) {
            int k = k0 + aK + i;
            As[aK + i][aRow] = (m < M && k < K) ? A[(size_t)m * K + k] : 0.f;
        }
        {
            int k = k0 + bK;
            float4 v = make_float4(0.f, 0.f, 0.f, 0.f);
            if (k < K) v = *(const float4*)&g_Wc[k * N + bcol + bN];
            *(float4*)&Bs[bK][bN] = v;
        }
        __syncthreads();
#pragma unroll
        for (int kk = 0; kk < 8; kk++) {
            float a[8], b[8];
#pragma unroll
            for (int i = 0; i < 8; i++) a[i] = As[kk][tr + i];
#pragma unroll
            for (int j = 0; j < 8; j++) b[j] = Bs[kk][tc + j];
#pragma unroll
            for (int i = 0; i < 8; i++)
#pragma unroll
                for (int j = 0; j < 8; j++) acc[i][j] += a[i] * b[j];
        }
        __syncthreads();
    }

#pragma unroll
    for (int i = 0; i < 8; i++) {
        int m = brow + tr + i;
        if (m >= M) continue;
#pragma unroll
        for (int j = 0; j < 8; j += 4) {
            int n = bcol + tc + j;
            float4 o;
            o.x = acc[i][j + 0] + g_bc[n + 0];
            o.y = acc[i][j + 1] + g_bc[n + 1];
            o.z = acc[i][j + 2] + g_bc[n + 2];
            o.w = acc[i][j + 3] + g_bc[n + 3];
            *(float4*)&g_PQ[(size_t)m * N + n] = o;
        }
    }
}

// ---------------------------------------------------------------------------
// Kernel 3: per-edge. Warp per edge; lane l owns channels [4l, 4l+4).
// out[e] = sum_c w2[c] * leaky(P[src][c] + Q[dst][c]) + b2
// ---------------------------------------------------------------------------
__global__ __launch_bounds__(256) void edge_kernel(
    const int* __restrict__ src, const int* __restrict__ dst,
    const float* __restrict__ W_a2,   // [128]
    const float* __restrict__ b_a2,   // [1]
    float* __restrict__ out, int E) {
    int warp = (blockIdx.x * blockDim.x + threadIdx.x) >> 5;
    int lane = threadIdx.x & 31;
    if (warp >= E) return;

    int s = src[warp];
    int d = dst[warp];

    const float4* PQ4 = (const float4*)g_PQ;   // 64 float4 per node row
    float4 p = PQ4[(size_t)s * 64 + lane];         // P half
    float4 q = PQ4[(size_t)d * 64 + 32 + lane];    // Q half
    float4 w = *(const float4*)&W_a2[lane * 4];

    float x0 = p.x + q.x; x0 = (x0 > 0.f) ? x0 : 0.01f * x0;
    float x1 = p.y + q.y; x1 = (x1 > 0.f) ? x1 : 0.01f * x1;
    float x2 = p.z + q.z; x2 = (x2 > 0.f) ? x2 : 0.01f * x2;
    float x3 = p.w + q.w; x3 = (x3 > 0.f) ? x3 : 0.01f * x3;

    float acc = x0 * w.x + x1 * w.y + x2 * w.z + x3 * w.w;
#pragma unroll
    for (int off = 16; off; off >>= 1)
        acc += __shfl_xor_sync(0xFFFFFFFFu, acc, off);

    if (lane == 0) out[warp] = acc + b_a2[0];
}

// ---------------------------------------------------------------------------
extern "C" void kernel_launch(void* const* d_in, const int* in_sizes, int n_in,
                              void* d_out, int out_size) {
    const float* node_feat = (const float*)d_in[0];
    const int*   src       = (const int*)  d_in[2];
    const int*   dst       = (const int*)  d_in[3];
    const float* W_node    = (const float*)d_in[4];
    const float* b_node    = (const float*)d_in[5];
    const float* W_a1      = (const float*)d_in[8];
    const float* b_a1      = (const float*)d_in[9];
    const float* W_a2      = (const float*)d_in[10];
    const float* b_a2      = (const float*)d_in[11];
    float* out = (float*)d_out;

    int E = in_sizes[2];
    int K = in_sizes[4] / CH;        // 118
    int M = in_sizes[0] / K;         // 10000

    build_wc_kernel<<<2 * CH, CH>>>(W_node, b_node, W_a1, b_a1, K);

    dim3 grid((M + 127) / 128, 2);
    sgemm_bias_kernel<<<grid, 256>>>(node_feat, M, K);

    int blocks = (E + 7) / 8;        // 8 warps (edges) per 256-thread block
    edge_kernel<<<blocks, 256>>>(src, dst, W_a2, b_a2, out, E);
}

// round 2
// speedup vs baseline: 1.3548x; 1.3548x over previous
#include <cuda_runtime.h>
#include <cuda_fp16.h>
#include <cstdint>

// ---------------------------------------------------------------------------
// GATv2 collapsed:
//   out[e] = leaky_relu( P[src[e]] + Q[dst[e]] ) . w2 + b2
// where   PQ = node_feat @ Wc + bc   (Wc = W_node @ [W1_top | W1_bot], folded bias)
// Layer loop is idempotent; edge-hidden path is dead code.
// PQ stored in fp16 to halve the L2-bound edge-gather traffic.
// ---------------------------------------------------------------------------

#define CH 128
#define MAX_NODES 10240
#define MAX_K 128

__device__ __half g_PQh[MAX_NODES * 2 * CH];   // per node: [P(128) | Q(128)] fp16
__device__ float  g_Wc[MAX_K * 2 * CH];        // combined weight [K, 256]
__device__ float  g_bc[2 * CH];                // combined bias   [256]

// packed fp32x2 FMA (Blackwell): d = a*b + c elementwise on 2 floats
__device__ __forceinline__ void fma_f32x2(unsigned long long& d,
                                          unsigned long long a,
                                          unsigned long long b,
                                          unsigned long long c) {
    asm("fma.rn.f32x2 %0, %1, %2, %3;" : "=l"(d) : "l"(a), "l"(b), "l"(c));
}
__device__ __forceinline__ unsigned long long pack_f32x2(float lo, float hi) {
    unsigned long long r;
    asm("mov.b64 %0, {%1, %2};" : "=l"(r) : "r"(__float_as_uint(lo)), "r"(__float_as_uint(hi)));
    return r;
}
__device__ __forceinline__ void unpack_f32x2(unsigned long long v, float& lo, float& hi) {
    unsigned int a, b;
    asm("mov.b64 {%0, %1}, %2;" : "=r"(a), "=r"(b) : "l"(v));
    lo = __uint_as_float(a);
    hi = __uint_as_float(b);
}

// ---------------------------------------------------------------------------
// Kernel 1: build combined weights. Block j (0..255) owns output column j.
// Stage the W_a1 column in smem once, then warp-parallel float4 dots over rows.
// Row k == K computes the folded bias from b_node.
// ---------------------------------------------------------------------------
__global__ __launch_bounds__(128) void build_wc_kernel(
    const float* __restrict__ W_node,   // [K,128]
    const float* __restrict__ b_node,   // [128]
    const float* __restrict__ W_a1,     // [256,128]
    const float* __restrict__ b_a1,     // [128]
    int K) {
    int j    = blockIdx.x;       // 0..255
    int half = j >> 7;
    int c0   = j & (CH - 1);
    __shared__ float Bs[CH];
    int t = threadIdx.x;         // 0..127
    Bs[t] = W_a1[(half * CH + t) * CH + c0];
    __syncthreads();

    int lane = t & 31;
    int w    = t >> 5;           // 4 warps

    float4 bv = ((const float4*)Bs)[lane];

    for (int k = w; k <= K; k += 4) {
        const float* arow = (k < K) ? (W_node + k * CH) : b_node;
        float4 av = ((const float4*)arow)[lane];
        float acc = av.x * bv.x + av.y * bv.y + av.z * bv.z + av.w * bv.w;
#pragma unroll
        for (int off = 16; off; off >>= 1)
            acc += __shfl_xor_sync(0xFFFFFFFFu, acc, off);
        if (lane == 0) {
            if (k < K) g_Wc[k * (2 * CH) + j] = acc;
            else       g_bc[j] = acc + (half ? b_a1[c0] : 0.f);
        }
    }
}

// ---------------------------------------------------------------------------
// Kernel 2: SGEMM  PQ[M,256] = node_feat[M,K] @ g_Wc[K,256] + g_bc  -> fp16
// 128x128 tile, BK=8, 8x8 per thread via fp32x2 packed FMA, 256 threads.
// ---------------------------------------------------------------------------
__global__ __launch_bounds__(256) void sgemm_bias_kernel(
    const float* __restrict__ A, int M, int K) {
    const int N = 2 * CH;
    __shared__ __align__(16) float As[8][128];
    __shared__ __align__(16) float Bs[8][128];

    int brow = blockIdx.x * 128;
    int bcol = blockIdx.y * 128;
    int tid  = threadIdx.x;
    int tr   = (tid >> 4) * 8;       // 0..120
    int tc   = (tid & 15) * 8;       // 0..120

    unsigned long long acc64[8][4];
#pragma unroll
    for (int i = 0; i < 8; i++)
#pragma unroll
        for (int j = 0; j < 4; j++) acc64[i][j] = 0ull;

    int aRow = tid >> 1;             // 0..127
    int aK   = (tid & 1) * 4;        // 0 or 4
    int bK   = tid >> 5;             // 0..7
    int bN   = (tid & 31) * 4;       // 0..124

    for (int k0 = 0; k0 < K; k0 += 8) {
        int m = brow + aRow;
#pragma unroll
        for (int i = 0; i < 4; i++) {
            int k = k0 + aK + i;
            As[aK + i][aRow] = (m < M && k < K) ? A[(size_t)m * K + k] : 0.f;
        }
        {
            int k = k0 + bK;
            float4 v = make_float4(0.f, 0.f, 0.f, 0.f);
            if (k < K) v = *(const float4*)&g_Wc[k * N + bcol + bN];
            *(float4*)&Bs[bK][bN] = v;
        }
        __syncthreads();
#pragma unroll
        for (int kk = 0; kk < 8; kk++) {
            float a[8];
            *(float4*)&a[0] = *(const float4*)&As[kk][tr];
            *(float4*)&a[4] = *(const float4*)&As[kk][tr + 4];
            ulonglong2 t0 = *(const ulonglong2*)&Bs[kk][tc];
            ulonglong2 t1 = *(const ulonglong2*)&Bs[kk][tc + 4];
            unsigned long long b64[4] = {t0.x, t0.y, t1.x, t1.y};
#pragma unroll
            for (int i = 0; i < 8; i++) {
                unsigned long long aa = pack_f32x2(a[i], a[i]);
#pragma unroll
                for (int j = 0; j < 4; j++)
                    fma_f32x2(acc64[i][j], aa, b64[j], acc64[i][j]);
            }
        }
        __syncthreads();
    }

#pragma unroll
    for (int i = 0; i < 8; i++) {
        int m = brow + tr + i;
        if (m >= M) continue;
        __half2* orow = (__half2*)&g_PQh[(size_t)m * N + bcol + tc];
#pragma unroll
        for (int j = 0; j < 4; j++) {
            int n = bcol + tc + 2 * j;
            float lo, hi;
            unpack_f32x2(acc64[i][j], lo, hi);
            lo += g_bc[n];
            hi += g_bc[n + 1];
            orow[j] = __floats2half2_rn(lo, hi);
        }
    }
}

// ---------------------------------------------------------------------------
// Kernel 3: per-edge. 16 lanes per edge (2 edges/warp); lane owns 8 channels
// via one uint4 (8 halves) load per operand. fp32 accumulate + leaky.
// ---------------------------------------------------------------------------
__global__ __launch_bounds__(256) void edge_kernel(
    const int* __restrict__ src, const int* __restrict__ dst,
    const float* __restrict__ W_a2,   // [128]
    const float* __restrict__ b_a2,   // [1]
    float* __restrict__ out, int E) {
    int gwarp = (blockIdx.x * blockDim.x + threadIdx.x) >> 5;
    int lane  = threadIdx.x & 31;
    int sub   = lane & 15;
    int e     = gwarp * 2 + (lane >> 4);

    bool valid = (e < E);
    int ec = valid ? e : 0;
    int s = src[ec];
    int d = dst[ec];

    const uint4* PQ = (const uint4*)g_PQh;          // 32 uint4 per node row
    uint4 pv = PQ[(size_t)s * 32 + sub];            // P channels sub*8..+7
    uint4 qv = PQ[(size_t)d * 32 + 16 + sub];       // Q channels sub*8..+7
    float4 w0 = ((const float4*)W_a2)[sub * 2];
    float4 w1 = ((const float4*)W_a2)[sub * 2 + 1];

    const __half2* ph = (const __half2*)&pv;
    const __half2* qh = (const __half2*)&qv;
    float wv[8] = {w0.x, w0.y, w0.z, w0.w, w1.x, w1.y, w1.z, w1.w};

    float acc = 0.f;
#pragma unroll
    for (int i = 0; i < 4; i++) {
        float2 a = __half22float2(ph[i]);
        float2 b = __half22float2(qh[i]);
        float x = a.x + b.x; x = fmaxf(x, 0.01f * x);   // leaky_relu
        float y = a.y + b.y; y = fmaxf(y, 0.01f * y);
        acc = fmaf(x, wv[2 * i],     acc);
        acc = fmaf(y, wv[2 * i + 1], acc);
    }
    acc += __shfl_xor_sync(0xFFFFFFFFu, acc, 8);
    acc += __shfl_xor_sync(0xFFFFFFFFu, acc, 4);
    acc += __shfl_xor_sync(0xFFFFFFFFu, acc, 2);
    acc += __shfl_xor_sync(0xFFFFFFFFu, acc, 1);

    if (valid && sub == 0) out[e] = acc + b_a2[0];
}

// ---------------------------------------------------------------------------
extern "C" void kernel_launch(void* const* d_in, const int* in_sizes, int n_in,
                              void* d_out, int out_size) {
    const float* node_feat = (const float*)d_in[0];
    const int*   src       = (const int*)  d_in[2];
    const int*   dst       = (const int*)  d_in[3];
    const float* W_node    = (const float*)d_in[4];
    const float* b_node    = (const float*)d_in[5];
    const float* W_a1      = (const float*)d_in[8];
    const float* b_a1      = (const float*)d_in[9];
    const float* W_a2      = (const float*)d_in[10];
    const float* b_a2      = (const float*)d_in[11];
    float* out = (float*)d_out;

    int E = in_sizes[2];
    int K = in_sizes[4] / CH;        // 118
    int M = in_sizes[0] / K;         // 10000

    build_wc_kernel<<<2 * CH, CH>>>(W_node, b_node, W_a1, b_a1, K);

    dim3 grid((M + 127) / 128, 2);
    sgemm_bias_kernel<<<grid, 256>>>(node_feat, M, K);

    int blocks = (E * 16 + 255) / 256;   // 2 edges per warp, 16 per block
    edge_kernel<<<blocks, 256>>>(src, dst, W_a2, b_a2, out, E);
}

// round 3
// speedup vs baseline: 1.4572x; 1.0756x over previous
#include <cuda_runtime.h>
#include <cuda_fp16.h>
#include <cstdint>

// ---------------------------------------------------------------------------
// GATv2 collapsed:
//   out[e] = leaky_relu( P[src[e]] + Q[dst[e]] ) . w2 + b2
//   PQ = node_feat @ Wc + bc,  Wc = W_node @ [W1_top | W1_bot] (biases folded)
// Layer loop idempotent; edge-hidden path dead. PQ stored fp16 (L2 traffic /2).
// ---------------------------------------------------------------------------

#define CH 128
#define MAX_NODES 10240
#define MAX_K 128

__device__ __half g_PQh[MAX_NODES * 2 * CH];   // per node: [P(128) | Q(128)] fp16
__device__ float  g_Wc[MAX_K * 2 * CH];        // combined weight [K, 256]
__device__ float  g_bc[2 * CH];                // combined bias   [256]

// packed fp32x2 FMA (Blackwell)
__device__ __forceinline__ void fma_f32x2(unsigned long long& d,
                                          unsigned long long a,
                                          unsigned long long b,
                                          unsigned long long c) {
    asm("fma.rn.f32x2 %0, %1, %2, %3;" : "=l"(d) : "l"(a), "l"(b), "l"(c));
}
__device__ __forceinline__ unsigned long long pack_f32x2(float lo, float hi) {
    unsigned long long r;
    asm("mov.b64 %0, {%1, %2};" : "=l"(r) : "r"(__float_as_uint(lo)), "r"(__float_as_uint(hi)));
    return r;
}
__device__ __forceinline__ void unpack_f32x2(unsigned long long v, float& lo, float& hi) {
    unsigned int a, b;
    asm("mov.b64 {%0, %1}, %2;" : "=r"(a), "=r"(b) : "l"(v));
    lo = __uint_as_float(a);
    hi = __uint_as_float(b);
}

// ---------------------------------------------------------------------------
// Kernel 1: Wc[119x256] = [W_node; b_node] @ W_a1'  as a proper tiled GEMM.
// Block = 32 k-rows x 64 j-cols, 256 threads, A+B fully staged in smem
// (coalesced; B read along W_a1 ROWS), 8 outputs/thread, no shuffles.
// Row K (==118) is the bias row; g_bc gets +b_a1 on the Q half.
// ---------------------------------------------------------------------------
__global__ __launch_bounds__(256) void build_wc_kernel(
    const float* __restrict__ W_node,   // [K,128]
    const float* __restrict__ b_node,   // [128]
    const float* __restrict__ W_a1,     // [256,128]
    const float* __restrict__ b_a1,     // [128]
    int K) {
    __shared__ __align__(16) float As[32][128];   // 16 KB
    __shared__ __align__(16) float Bs[128][64];   // 32 KB  (total 48 KB exact)

    int tid   = threadIdx.x;
    int kbase = blockIdx.x * 32;
    int jbase = blockIdx.y * 64;          // 0,64,128,192 — stays within one half
    int half  = jbase >> 7;
    int jloc  = jbase & (CH - 1);         // 0 or 64

    // Load A tile: 32 rows x 128 floats = 1024 float4, 4 per thread.
#pragma unroll
    for (int i = 0; i < 4; i++) {
        int id  = tid + i * 256;
        int r   = id >> 5;                // 0..31
        int c4  = id & 31;                // float4 index within row
        int k   = kbase + r;
        float4 v = make_float4(0.f, 0.f, 0.f, 0.f);
        if (k < K)       v = ((const float4*)(W_node + (size_t)k * CH))[c4];
        else if (k == K) v = ((const float4*)b_node)[c4];
        *(float4*)&As[r][c4 * 4] = v;
    }
    // Load B tile: rows c=0..127 of W_a1 half, cols [jloc, jloc+64) -> coalesced.
#pragma unroll
    for (int i = 0; i < 8; i++) {
        int id  = tid + i * 256;
        int c   = id >> 4;                // 0..127
        int j4  = id & 15;                // float4 within 64-col slice
        float4 v = ((const float4*)(W_a1 + (size_t)(half * CH + c) * CH + jloc))[j4];
        *(float4*)&Bs[c][j4 * 4] = v;
    }
    __syncthreads();

    int cx = tid & 31;                    // cols cx, cx+32
    int ry = tid >> 5;                    // rows ry, ry+8, ry+16, ry+24
    float acc[4][2] = {};
#pragma unroll 4
    for (int k = 0; k < 128; k++) {
        float b0 = Bs[k][cx];
        float b1 = Bs[k][cx + 32];
#pragma unroll
        for (int i = 0; i < 4; i++) {
            float a = As[ry + 8 * i][k];
            acc[i][0] = fmaf(a, b0, acc[i][0]);
            acc[i][1] = fmaf(a, b1, acc[i][1]);
        }
    }

#pragma unroll
    for (int i = 0; i < 4; i++) {
        int k = kbase + ry + 8 * i;
#pragma unroll
        for (int j = 0; j < 2; j++) {
            int jj = jbase + cx + 32 * j;
            if (k < K) {
                g_Wc[(size_t)k * (2 * CH) + jj] = acc[i][j];
            } else if (k == K) {
                g_bc[jj] = acc[i][j] + (half ? b_a1[jj - CH] : 0.f);
            }
        }
    }
}

// ---------------------------------------------------------------------------
// Kernel 2: SGEMM  PQ[M,256] = node_feat[M,K] @ g_Wc[K,256] + g_bc  -> fp16
// 128x128 tile, BK=8, 8x8 per thread via fp32x2 packed FMA, 256 threads.
// ---------------------------------------------------------------------------
__global__ __launch_bounds__(256) void sgemm_bias_kernel(
    const float* __restrict__ A, int M, int K) {
    const int N = 2 * CH;
    __shared__ __align__(16) float As[8][128];
    __shared__ __align__(16) float Bs[8][128];

    int brow = blockIdx.x * 128;
    int bcol = blockIdx.y * 128;
    int tid  = threadIdx.x;
    int tr   = (tid >> 4) * 8;
    int tc   = (tid & 15) * 8;

    unsigned long long acc64[8][4];
#pragma unroll
    for (int i = 0; i < 8; i++)
#pragma unroll
        for (int j = 0; j < 4; j++) acc64[i][j] = 0ull;

    int aRow = tid >> 1;
    int aK   = (tid & 1) * 4;
    int bK   = tid >> 5;
    int bN   = (tid & 31) * 4;

    for (int k0 = 0; k0 < K; k0 += 8) {
        int m = brow + aRow;
#pragma unroll
        for (int i = 0; i < 4; i++) {
            int k = k0 + aK + i;
            As[aK + i][aRow] = (m < M && k < K) ? A[(size_t)m * K + k] : 0.f;
        }
        {
            int k = k0 + bK;
            float4 v = make_float4(0.f, 0.f, 0.f, 0.f);
            if (k < K) v = *(const float4*)&g_Wc[k * N + bcol + bN];
            *(float4*)&Bs[bK][bN] = v;
        }
        __syncthreads();
#pragma unroll
        for (int kk = 0; kk < 8; kk++) {
            float a[8];
            *(float4*)&a[0] = *(const float4*)&As[kk][tr];
            *(float4*)&a[4] = *(const float4*)&As[kk][tr + 4];
            ulonglong2 t0 = *(const ulonglong2*)&Bs[kk][tc];
            ulonglong2 t1 = *(const ulonglong2*)&Bs[kk][tc + 4];
            unsigned long long b64[4] = {t0.x, t0.y, t1.x, t1.y};
#pragma unroll
            for (int i = 0; i < 8; i++) {
                unsigned long long aa = pack_f32x2(a[i], a[i]);
#pragma unroll
                for (int j = 0; j < 4; j++)
                    fma_f32x2(acc64[i][j], aa, b64[j], acc64[i][j]);
            }
        }
        __syncthreads();
    }

#pragma unroll
    for (int i = 0; i < 8; i++) {
        int m = brow + tr + i;
        if (m >= M) continue;
        __half2* orow = (__half2*)&g_PQh[(size_t)m * N + bcol + tc];
#pragma unroll
        for (int j = 0; j < 4; j++) {
            int n = bcol + tc + 2 * j;
            float lo, hi;
            unpack_f32x2(acc64[i][j], lo, hi);
            lo += g_bc[n];
            hi += g_bc[n + 1];
            orow[j] = __floats2half2_rn(lo, hi);
        }
    }
}

// ---------------------------------------------------------------------------
// Kernel 3: per-edge. 16 lanes per edge (2 edges/warp); lane owns 8 channels
// via one uint4 (8 halves) per operand. half2 add+leaky, fp32 dot+reduce.
// ---------------------------------------------------------------------------
__global__ __launch_bounds__(256) void edge_kernel(
    const int* __restrict__ src, const int* __restrict__ dst,
    const float* __restrict__ W_a2,   // [128]
    const float* __restrict__ b_a2,   // [1]
    float* __restrict__ out, int E) {
    int gwarp = (blockIdx.x * blockDim.x + threadIdx.x) >> 5;
    int lane  = threadIdx.x & 31;
    int sub   = lane & 15;
    int e     = gwarp * 2 + (lane >> 4);

    bool valid = (e < E);
    int ec = valid ? e : 0;
    int s = src[ec];
    int d = dst[ec];

    const uint4* PQ = (const uint4*)g_PQh;          // 32 uint4 per node row
    uint4 pv = PQ[(size_t)s * 32 + sub];            // P channels sub*8..+7
    uint4 qv = PQ[(size_t)d * 32 + 16 + sub];       // Q channels sub*8..+7
    float4 w0 = ((const float4*)W_a2)[sub * 2];
    float4 w1 = ((const float4*)W_a2)[sub * 2 + 1];

    const __half2* ph = (const __half2*)&pv;
    const __half2* qh = (const __half2*)&qv;
    float wv[8] = {w0.x, w0.y, w0.z, w0.w, w1.x, w1.y, w1.z, w1.w};

    const __half2 slope = __float2half2_rn(0.01f);
    float acc = 0.f;
#pragma unroll
    for (int i = 0; i < 4; i++) {
        __half2 x = __hadd2(ph[i], qh[i]);
        x = __hmax2(x, __hmul2(x, slope));          // leaky_relu
        float2 f = __half22float2(x);
        acc = fmaf(f.x, wv[2 * i],     acc);
        acc = fmaf(f.y, wv[2 * i + 1], acc);
    }
    acc += __shfl_xor_sync(0xFFFFFFFFu, acc, 8);
    acc += __shfl_xor_sync(0xFFFFFFFFu, acc, 4);
    acc += __shfl_xor_sync(0xFFFFFFFFu, acc, 2);
    acc += __shfl_xor_sync(0xFFFFFFFFu, acc, 1);

    if (valid && sub == 0) out[e] = acc + b_a2[0];
}

// ---------------------------------------------------------------------------
extern "C" void kernel_launch(void* const* d_in, const int* in_sizes, int n_in,
                              void* d_out, int out_size) {
    const float* node_feat = (const float*)d_in[0];
    const int*   src       = (const int*)  d_in[2];
    const int*   dst       = (const int*)  d_in[3];
    const float* W_node    = (const float*)d_in[4];
    const float* b_node    = (const float*)d_in[5];
    const float* W_a1      = (const float*)d_in[8];
    const float* b_a1      = (const float*)d_in[9];
    const float* W_a2      = (const float*)d_in[10];
    const float* b_a2      = (const float*)d_in[11];
    float* out = (float*)d_out;

    int E = in_sizes[2];
    int K = in_sizes[4] / CH;        // 118
    int M = in_sizes[0] / K;         // 10000

    {   // (K+1) rows incl. bias row -> 32-row tiles; 256 cols -> 64-col tiles
        dim3 g((K + 1 + 31) / 32, 4);
        build_wc_kernel<<<g, 256>>>(W_node, b_node, W_a1, b_a1, K);
    }
    {
        dim3 g((M + 127) / 128, 2);
        sgemm_bias_kernel<<<g, 256>>>(node_feat, M, K);
    }
    {
        int blocks = (E * 16 + 255) / 256;   // 2 edges/warp
        edge_kernel<<<blocks, 256>>>(src, dst, W_a2, b_a2, out, E);
    }
}